// round 2
// baseline (speedup 1.0000x reference)
#include <cuda_runtime.h>
#include <math.h>

// Problem constants
#define NB 32
#define NC 256
#define NH 56
#define NW 56
#define NG 2
#define NK 7
#define NP 49
#define CMID 64
#define COUT2 512
#define NSL 4            // conv1 split-K slices (64 channels each)

typedef unsigned long long ull;

__device__ __forceinline__ ull pack2(float a, float b) {
    ull r;
    asm("mov.b64 %0, {%1, %2};" : "=l"(r) : "f"(a), "f"(b));
    return r;
}
__device__ __forceinline__ void fma2(ull& d, ull a, ull b) {
    asm("fma.rn.f32x2 %0, %1, %2, %0;" : "+l"(d) : "l"(a), "l"(b));
}
__device__ __forceinline__ void unpack2(ull v, float& lo, float& hi) {
    asm("mov.b64 {%0, %1}, %2;" : "=f"(lo), "=f"(hi) : "l"(v));
}

// ---------------- scratch ----------------
__device__ float g_pooled[NB * NC * NP];
__device__ float g_w1t[2304 * CMID];            // [k=c*9+t][oc]
__device__ float g_w2t[576 * COUT2];            // [k=c*9+t][oc]
__device__ float g_c1part[NB * CMID * NP * NSL];
__device__ float g_hmid[NB * CMID * NP];
__device__ float g_logits[NB * COUT2 * NP];
__device__ float g_dynw[NB * NC * NP];

// ---------------- weight transpose (tiny, runs once per replay) ----------------
#define W1N (CMID * 2304)
#define W2N (COUT2 * 576)
__global__ void wt_kernel(const float* __restrict__ w1, const float* __restrict__ w2) {
    int i = blockIdx.x * 256 + threadIdx.x;
    if (i < W1N) {
        int oc = i / 2304, k = i % 2304;
        g_w1t[k * CMID + oc] = w1[i];
    } else {
        int j = i - W1N;
        if (j < W2N) {
            int oc = j / 576, k = j % 576;
            g_w2t[k * COUT2 + oc] = w2[j];
        }
    }
}

// ---------------- kernel 1: adaptive avg pool 56x56 -> 7x7 ----------------
__global__ void pool_kernel(const float* __restrict__ x) {
    __shared__ float srow[392];
    const int bc = blockIdx.x;
    const int tid = threadIdx.x;
    if (tid < 392) {
        const int r = tid / 7, s = tid % 7;
        const float4* p = reinterpret_cast<const float4*>(
            x + (size_t)bc * (NH * NW) + r * NW + s * 8);
        float4 v0 = p[0], v1 = p[1];
        srow[tid] = (v0.x + v0.y + v0.z + v0.w) + (v1.x + v1.y + v1.z + v1.w);
    }
    __syncthreads();
    if (tid < NP) {
        const int wi = tid / 7, wj = tid % 7;
        float s = 0.f;
#pragma unroll
        for (int k = 0; k < 8; k++) s += srow[(wi * 8 + k) * 7 + wj];
        g_pooled[bc * NP + tid] = s * (1.0f / 64.0f);
    }
}

// ---------------- kernel 2: conv1 3x3 (256->64), split-K, f32x2 ----------------
// grid (4 slices, 32 batches), block 224 (7 warps = 7 output rows; lane = oc-pair)
__global__ void __launch_bounds__(224) conv1_kernel() {
    __shared__ float s_act[64 * 108];   // 64 ch x 9 rows x 12 (padded), cols 0..8 valid
    __shared__ float s_w[72 * 64];      // 8-ch chunk: (cl*9+t) x 64 oc
    const int sl = blockIdx.x, b = blockIdx.y;
    const int tid = threadIdx.x;
    const int r = tid >> 5, lane = tid & 31;

    for (int idx = tid; idx < 64 * 81; idx += 224) {
        const int c = idx / 81, pp = idx % 81;
        const int pr = pp / 9, pc = pp % 9;
        float v = 0.f;
        if (pr >= 1 && pr <= 7 && pc >= 1 && pc <= 7)
            v = g_pooled[(b * NC + sl * 64 + c) * NP + (pr - 1) * 7 + (pc - 1)];
        s_act[c * 108 + pr * 12 + pc] = v;
    }

    ull acc[7];
#pragma unroll
    for (int i = 0; i < 7; i++) acc[i] = 0ull;

    for (int chunk = 0; chunk < 8; chunk++) {
        __syncthreads();
        for (int idx = tid; idx < 72 * 64; idx += 224) {
            const int kk = idx >> 6, oc = idx & 63;
            s_w[idx] = g_w1t[((sl * 64 + chunk * 8) * 9 + kk) * CMID + oc];
        }
        __syncthreads();

#pragma unroll
        for (int cl = 0; cl < 8; cl++) {
            const int c = chunk * 8 + cl;
            ull aa[3][9];
#pragma unroll
            for (int ti = 0; ti < 3; ti++) {
                const float* rp = s_act + c * 108 + (r + ti) * 12;
                float4 v0 = *reinterpret_cast<const float4*>(rp);
                float4 v1 = *reinterpret_cast<const float4*>(rp + 4);
                float f8 = rp[8];
                aa[ti][0] = pack2(v0.x, v0.x); aa[ti][1] = pack2(v0.y, v0.y);
                aa[ti][2] = pack2(v0.z, v0.z); aa[ti][3] = pack2(v0.w, v0.w);
                aa[ti][4] = pack2(v1.x, v1.x); aa[ti][5] = pack2(v1.y, v1.y);
                aa[ti][6] = pack2(v1.z, v1.z); aa[ti][7] = pack2(v1.w, v1.w);
                aa[ti][8] = pack2(f8, f8);
            }
#pragma unroll
            for (int ti = 0; ti < 3; ti++) {
#pragma unroll
                for (int tj = 0; tj < 3; tj++) {
                    const ull w01 = *reinterpret_cast<const ull*>(
                        s_w + (cl * 9 + ti * 3 + tj) * 64 + lane * 2);
#pragma unroll
                    for (int pj = 0; pj < 7; pj++)
                        fma2(acc[pj], aa[ti][pj + tj], w01);
                }
            }
        }
    }
#pragma unroll
    for (int pj = 0; pj < 7; pj++) {
        float v0, v1;
        unpack2(acc[pj], v0, v1);
        const int p = r * 7 + pj;
        g_c1part[((size_t)(b * CMID + lane * 2) * NP + p) * NSL + sl] = v0;
        g_c1part[((size_t)(b * CMID + lane * 2 + 1) * NP + p) * NSL + sl] = v1;
    }
}

// ---------------- kernel 3: reduce partials + BN + exact GELU ----------------
__global__ void ep1_kernel(const float* __restrict__ gamma, const float* __restrict__ beta) {
    const int idx = blockIdx.x * 256 + threadIdx.x;
    const int oc = (idx / NP) & (CMID - 1);
    float4 v = *reinterpret_cast<const float4*>(g_c1part + (size_t)idx * NSL);
    float s = (v.x + v.y) + (v.z + v.w);
    float h = s * (gamma[oc] * rsqrtf(1.0f + 1e-5f)) + beta[oc];
    g_hmid[idx] = 0.5f * h * (1.0f + erff(h * 0.70710678118654752f));
}

// ---------------- kernel 4: conv2 3x3 (64->512) + bias, f32x2 ----------------
// grid (4 oc-tiles of 128, 32 batches), block 224
__global__ void __launch_bounds__(224) conv2_kernel(const float* __restrict__ b2) {
    __shared__ float s_act[64 * 108];   // 64 ch x 9x12 padded
    __shared__ float s_w[36 * 128];     // 4-ch chunk: (cl*9+t) x 128 oc
    const int ot = blockIdx.x, b = blockIdx.y;
    const int tid = threadIdx.x;
    const int r = tid >> 5, lane = tid & 31;

    for (int idx = tid; idx < 64 * 81; idx += 224) {
        const int c = idx / 81, pp = idx % 81;
        const int pr = pp / 9, pc = pp % 9;
        float v = 0.f;
        if (pr >= 1 && pr <= 7 && pc >= 1 && pc <= 7)
            v = g_hmid[(b * CMID + c) * NP + (pr - 1) * 7 + (pc - 1)];
        s_act[c * 108 + pr * 12 + pc] = v;
    }

    ull acc0[7], acc1[7];
#pragma unroll
    for (int i = 0; i < 7; i++) { acc0[i] = 0ull; acc1[i] = 0ull; }

    for (int chunk = 0; chunk < 16; chunk++) {
        __syncthreads();
        for (int idx = tid; idx < 36 * 128; idx += 224) {
            const int kk = idx >> 7, oc = idx & 127;
            s_w[idx] = g_w2t[(chunk * 36 + kk) * COUT2 + ot * 128 + oc];
        }
        __syncthreads();

#pragma unroll
        for (int cl = 0; cl < 4; cl++) {
            const int c = chunk * 4 + cl;
            ull aa[3][9];
#pragma unroll
            for (int ti = 0; ti < 3; ti++) {
                const float* rp = s_act + c * 108 + (r + ti) * 12;
                float4 v0 = *reinterpret_cast<const float4*>(rp);
                float4 v1 = *reinterpret_cast<const float4*>(rp + 4);
                float f8 = rp[8];
                aa[ti][0] = pack2(v0.x, v0.x); aa[ti][1] = pack2(v0.y, v0.y);
                aa[ti][2] = pack2(v0.z, v0.z); aa[ti][3] = pack2(v0.w, v0.w);
                aa[ti][4] = pack2(v1.x, v1.x); aa[ti][5] = pack2(v1.y, v1.y);
                aa[ti][6] = pack2(v1.z, v1.z); aa[ti][7] = pack2(v1.w, v1.w);
                aa[ti][8] = pack2(f8, f8);
            }
#pragma unroll
            for (int ti = 0; ti < 3; ti++) {
#pragma unroll
                for (int tj = 0; tj < 3; tj++) {
                    const ulonglong2 wv = *reinterpret_cast<const ulonglong2*>(
                        s_w + (cl * 9 + ti * 3 + tj) * 128 + lane * 4);
#pragma unroll
                    for (int pj = 0; pj < 7; pj++) {
                        fma2(acc0[pj], aa[ti][pj + tj], wv.x);
                        fma2(acc1[pj], aa[ti][pj + tj], wv.y);
                    }
                }
            }
        }
    }

    const int oc0 = ot * 128 + lane * 4;
    const float4 bb = *reinterpret_cast<const float4*>(b2 + oc0);
#pragma unroll
    for (int pj = 0; pj < 7; pj++) {
        const int p = r * 7 + pj;
        float v0, v1, v2, v3;
        unpack2(acc0[pj], v0, v1);
        unpack2(acc1[pj], v2, v3);
        float* lp = g_logits + (size_t)(b * COUT2 + oc0) * NP + p;
        lp[0 * NP] = v0 + bb.x;
        lp[1 * NP] = v1 + bb.y;
        lp[2 * NP] = v2 + bb.z;
        lp[3 * NP] = v3 + bb.w;
    }
}

// ---------------- kernel 5: softmax over G=2 + mix kernel banks ----------------
__global__ void mix_kernel(const float* __restrict__ wdyn) {
    const int idx = blockIdx.x * 256 + threadIdx.x;
    const int b = idx / (NC * NP);
    const int rr = idx % (NC * NP);
    const int c = rr / NP, p = rr % NP;
    const float l0 = g_logits[((size_t)b * COUT2 + c) * NP + p];
    const float l1 = g_logits[((size_t)b * COUT2 + NC + c) * NP + p];
    const float m = fmaxf(l0, l1);
    const float e0 = expf(l0 - m), e1 = expf(l1 - m);
    const float w0 = wdyn[c * NP + p];
    const float w1 = wdyn[NC * NP + c * NP + p];
    g_dynw[idx] = (e0 * w0 + e1 * w1) / (e0 + e1);
}

// ---------------- kernel 6: per-(b,c) depthwise 7x7, f32x2 ----------------
// grid B*C, block 224 (4 row-groups x 56 cols); thread: 14 rows packed in 7 f32x2 accs
__global__ void __launch_bounds__(224) dw_kernel(const float* __restrict__ x,
                                                 float* __restrict__ y) {
    __shared__ float xs[62 * 62];
    __shared__ float ws[49];
    const int bc = blockIdx.x;
    const int tid = threadIdx.x;

    const float* xp = x + (size_t)bc * (NH * NW);
    for (int idx = tid; idx < 62 * 62; idx += 224) {
        const int rr = idx / 62, cc = idx % 62;
        const int gr = rr - 3, gc = cc - 3;
        float v = 0.f;
        if ((unsigned)gr < 56u && (unsigned)gc < 56u) v = xp[gr * 56 + gc];
        xs[idx] = v;
    }
    if (tid < 49) ws[tid] = g_dynw[(size_t)bc * NP + tid];
    __syncthreads();

    const int cg = tid / 56;
    const int col = tid % 56;

    ull acc[7];
#pragma unroll
    for (int k = 0; k < 7; k++) acc[k] = 0ull;

#pragma unroll
    for (int dj = 0; dj < 7; dj++) {
        float cv[20];
#pragma unroll
        for (int m = 0; m < 20; m++)
            cv[m] = xs[(cg * 14 + m) * 62 + col + dj];
        ull cvp[19];
#pragma unroll
        for (int m = 0; m < 19; m++)
            cvp[m] = pack2(cv[m], cv[m + 1]);
#pragma unroll
        for (int di = 0; di < 7; di++) {
            const float w = ws[di * 7 + dj];
            const ull ww = pack2(w, w);
#pragma unroll
            for (int k = 0; k < 7; k++)
                fma2(acc[k], cvp[2 * k + di], ww);
        }
    }
    float* yp = y + (size_t)bc * (NH * NW);
#pragma unroll
    for (int k = 0; k < 7; k++) {
        float v0, v1;
        unpack2(acc[k], v0, v1);
        yp[(cg * 14 + 2 * k) * 56 + col] = v0;
        yp[(cg * 14 + 2 * k + 1) * 56 + col] = v1;
    }
}

// ---------------- launch ----------------
extern "C" void kernel_launch(void* const* d_in, const int* in_sizes, int n_in,
                              void* d_out, int out_size) {
    const float* x     = (const float*)d_in[0];
    const float* wdyn  = (const float*)d_in[1];
    const float* w1    = (const float*)d_in[2];
    const float* gamma = (const float*)d_in[3];
    const float* beta  = (const float*)d_in[4];
    const float* w2    = (const float*)d_in[5];
    const float* b2    = (const float*)d_in[6];
    float* y = (float*)d_out;

    wt_kernel<<<(W1N + W2N + 255) / 256, 256>>>(w1, w2);
    pool_kernel<<<NB * NC, 416>>>(x);
    conv1_kernel<<<dim3(NSL, NB), 224>>>();
    ep1_kernel<<<392, 256>>>(gamma, beta);
    conv2_kernel<<<dim3(4, NB), 224>>>(b2);
    mix_kernel<<<1568, 256>>>(wdyn);
    dw_kernel<<<NB * NC, 224>>>(x, y);
}

// round 3
// speedup vs baseline: 1.4154x; 1.4154x over previous
#include <cuda_runtime.h>
#include <math.h>

// Problem constants
#define NB 32
#define NC 256
#define NH 56
#define NW 56
#define NP 49
#define CMID 64
#define NSL 4            // conv1 split-K slices (64 channels each)

// ---------------- scratch ----------------
__device__ float g_pooled[NB * NC * NP];
__device__ float g_w1t[2304 * CMID];            // [k = c*9+t][oc]
__device__ float g_w2d[576 * NC];               // [k = c*9+t][oc]  (diff: oc - (oc+256))
__device__ float g_b2d[NC];
__device__ float g_c1part[NB * CMID * NP * NSL];
__device__ float g_hmid[NB * CMID * NP];
__device__ float g_logitd[NB * NC * NP];        // l0 - l1 per (b, c, p)
__device__ float g_dynw[NB * NC * NP];

// ---------------- weight prep (runs each replay; tiny) ----------------
#define W1N (CMID * 2304)
#define W2DN (NC * 576)
__global__ void wt_kernel(const float* __restrict__ w1, const float* __restrict__ w2,
                          const float* __restrict__ b2) {
    int i = blockIdx.x * 256 + threadIdx.x;
    if (i < W1N) {
        int oc = i / 2304, k = i % 2304;
        g_w1t[k * CMID + oc] = w1[i];
    } else if (i < W1N + W2DN) {
        int j = i - W1N;
        int oc = j / 576, k = j % 576;
        g_w2d[k * NC + oc] = w2[oc * 576 + k] - w2[(oc + 256) * 576 + k];
    } else if (i < W1N + W2DN + NC) {
        int oc = i - W1N - W2DN;
        g_b2d[oc] = b2[oc] - b2[oc + 256];
    }
}

// ---------------- kernel 1: adaptive avg pool 56x56 -> 7x7 ----------------
__global__ void pool_kernel(const float* __restrict__ x) {
    __shared__ float srow[392];
    const int bc = blockIdx.x;
    const int tid = threadIdx.x;
    if (tid < 392) {
        const int r = tid / 7, s = tid % 7;
        const float4* p = reinterpret_cast<const float4*>(
            x + (size_t)bc * (NH * NW) + r * NW + s * 8);
        float4 v0 = p[0], v1 = p[1];
        srow[tid] = (v0.x + v0.y + v0.z + v0.w) + (v1.x + v1.y + v1.z + v1.w);
    }
    __syncthreads();
    if (tid < NP) {
        const int wi = tid / 7, wj = tid % 7;
        float s = 0.f;
#pragma unroll
        for (int k = 0; k < 8; k++) s += srow[(wi * 8 + k) * 7 + wj];
        g_pooled[bc * NP + tid] = s * (1.0f / 64.0f);
    }
}

// ---------------- kernel 2: conv1 3x3 (256->64), split-K, scalar FFMA ----------------
// grid (4 slices, 32 batches), block 224: warp = output row, lane = oc pair
__global__ void __launch_bounds__(224) conv1_kernel() {
    __shared__ float s_act[16 * 108];   // 16 ch x 9 rows x 12 cols (padded)
    __shared__ float s_w[144 * 64];     // 16-ch chunk: (cl*9+t) x 64 oc
    const int sl = blockIdx.x, b = blockIdx.y;
    const int tid = threadIdx.x;
    const int r = tid >> 5, lane = tid & 31;

    float acc0[7], acc1[7];
#pragma unroll
    for (int i = 0; i < 7; i++) { acc0[i] = 0.f; acc1[i] = 0.f; }

    for (int chunk = 0; chunk < 4; chunk++) {
        __syncthreads();
        for (int idx = tid; idx < 16 * 81; idx += 224) {
            const int c = idx / 81, pp = idx % 81;
            const int pr = pp / 9, pc = pp % 9;
            float v = 0.f;
            if (pr >= 1 && pr <= 7 && pc >= 1 && pc <= 7)
                v = g_pooled[(b * NC + sl * 64 + chunk * 16 + c) * NP + (pr - 1) * 7 + (pc - 1)];
            s_act[c * 108 + pr * 12 + pc] = v;
        }
        for (int idx = tid; idx < 144 * 64; idx += 224) {
            const int kk = idx >> 6, oc = idx & 63;
            s_w[idx] = g_w1t[((sl * 64 + chunk * 16) * 9 + kk) * CMID + oc];
        }
        __syncthreads();

#pragma unroll 4
        for (int cl = 0; cl < 16; cl++) {
            float aa[3][9];
#pragma unroll
            for (int ti = 0; ti < 3; ti++) {
                const float* rp = s_act + cl * 108 + (r + ti) * 12;
                float4 v0 = *reinterpret_cast<const float4*>(rp);
                float4 v1 = *reinterpret_cast<const float4*>(rp + 4);
                aa[ti][0] = v0.x; aa[ti][1] = v0.y; aa[ti][2] = v0.z; aa[ti][3] = v0.w;
                aa[ti][4] = v1.x; aa[ti][5] = v1.y; aa[ti][6] = v1.z; aa[ti][7] = v1.w;
                aa[ti][8] = rp[8];
            }
#pragma unroll
            for (int ti = 0; ti < 3; ti++) {
#pragma unroll
                for (int tj = 0; tj < 3; tj++) {
                    const float2 w = *reinterpret_cast<const float2*>(
                        s_w + (cl * 9 + ti * 3 + tj) * 64 + lane * 2);
#pragma unroll
                    for (int pj = 0; pj < 7; pj++) {
                        acc0[pj] = fmaf(aa[ti][pj + tj], w.x, acc0[pj]);
                        acc1[pj] = fmaf(aa[ti][pj + tj], w.y, acc1[pj]);
                    }
                }
            }
        }
    }
#pragma unroll
    for (int pj = 0; pj < 7; pj++) {
        const int p = r * 7 + pj;
        g_c1part[((size_t)(b * CMID + lane * 2) * NP + p) * NSL + sl] = acc0[pj];
        g_c1part[((size_t)(b * CMID + lane * 2 + 1) * NP + p) * NSL + sl] = acc1[pj];
    }
}

// ---------------- kernel 3: reduce partials + BN + exact GELU ----------------
__global__ void ep1_kernel(const float* __restrict__ gamma, const float* __restrict__ beta) {
    const int idx = blockIdx.x * 256 + threadIdx.x;
    const int oc = (idx / NP) & (CMID - 1);
    float4 v = *reinterpret_cast<const float4*>(g_c1part + (size_t)idx * NSL);
    float s = (v.x + v.y) + (v.z + v.w);
    float h = s * (gamma[oc] * rsqrtf(1.0f + 1e-5f)) + beta[oc];
    g_hmid[idx] = 0.5f * h * (1.0f + erff(h * 0.70710678118654752f));
}

// ---------------- kernel 4: conv2-diff 3x3 (64->256), scalar FFMA ----------------
// grid (4 oc-tiles of 64, 32 batches), block 224
__global__ void __launch_bounds__(224) conv2_kernel() {
    __shared__ float s_act[16 * 108];
    __shared__ float s_w[144 * 64];     // 16-ch chunk: (cl*9+t) x 64 oc
    const int ot = blockIdx.x, b = blockIdx.y;
    const int tid = threadIdx.x;
    const int r = tid >> 5, lane = tid & 31;

    float acc0[7], acc1[7];
#pragma unroll
    for (int i = 0; i < 7; i++) { acc0[i] = 0.f; acc1[i] = 0.f; }

    for (int chunk = 0; chunk < 4; chunk++) {
        __syncthreads();
        for (int idx = tid; idx < 16 * 81; idx += 224) {
            const int c = idx / 81, pp = idx % 81;
            const int pr = pp / 9, pc = pp % 9;
            float v = 0.f;
            if (pr >= 1 && pr <= 7 && pc >= 1 && pc <= 7)
                v = g_hmid[(b * CMID + chunk * 16 + c) * NP + (pr - 1) * 7 + (pc - 1)];
            s_act[c * 108 + pr * 12 + pc] = v;
        }
        for (int idx = tid; idx < 144 * 64; idx += 224) {
            const int kk = idx >> 6, oc = idx & 63;
            s_w[idx] = g_w2d[(chunk * 144 + kk) * NC + ot * 64 + oc];
        }
        __syncthreads();

#pragma unroll 4
        for (int cl = 0; cl < 16; cl++) {
            float aa[3][9];
#pragma unroll
            for (int ti = 0; ti < 3; ti++) {
                const float* rp = s_act + cl * 108 + (r + ti) * 12;
                float4 v0 = *reinterpret_cast<const float4*>(rp);
                float4 v1 = *reinterpret_cast<const float4*>(rp + 4);
                aa[ti][0] = v0.x; aa[ti][1] = v0.y; aa[ti][2] = v0.z; aa[ti][3] = v0.w;
                aa[ti][4] = v1.x; aa[ti][5] = v1.y; aa[ti][6] = v1.z; aa[ti][7] = v1.w;
                aa[ti][8] = rp[8];
            }
#pragma unroll
            for (int ti = 0; ti < 3; ti++) {
#pragma unroll
                for (int tj = 0; tj < 3; tj++) {
                    const float2 w = *reinterpret_cast<const float2*>(
                        s_w + (cl * 9 + ti * 3 + tj) * 64 + lane * 2);
#pragma unroll
                    for (int pj = 0; pj < 7; pj++) {
                        acc0[pj] = fmaf(aa[ti][pj + tj], w.x, acc0[pj]);
                        acc1[pj] = fmaf(aa[ti][pj + tj], w.y, acc1[pj]);
                    }
                }
            }
        }
    }

    const int oc0 = ot * 64 + lane * 2;
    const float bd0 = g_b2d[oc0], bd1 = g_b2d[oc0 + 1];
#pragma unroll
    for (int pj = 0; pj < 7; pj++) {
        const int p = r * 7 + pj;
        g_logitd[(size_t)(b * NC + oc0) * NP + p] = acc0[pj] + bd0;
        g_logitd[(size_t)(b * NC + oc0 + 1) * NP + p] = acc1[pj] + bd1;
    }
}

// ---------------- kernel 5: sigmoid gate + mix kernel banks ----------------
__global__ void mix_kernel(const float* __restrict__ wdyn) {
    const int idx = blockIdx.x * 256 + threadIdx.x;
    const int rr = idx % (NC * NP);
    const float ld = g_logitd[idx];                 // l0 - l1
    const float s = 1.0f / (1.0f + expf(-ld));      // softmax weight of bank 0
    const float w0 = wdyn[rr];
    const float w1 = wdyn[NC * NP + rr];
    g_dynw[idx] = s * w0 + (1.0f - s) * w1;
}

// ---------------- kernel 6: per-(b,c) depthwise 7x7, scalar FFMA ----------------
__global__ void __launch_bounds__(224) dw_kernel(const float* __restrict__ x,
                                                 float* __restrict__ y) {
    __shared__ float xs[62 * 62];
    __shared__ float ws[49];
    const int bc = blockIdx.x;
    const int tid = threadIdx.x;

    const float* xp = x + (size_t)bc * (NH * NW);
    for (int idx = tid; idx < 62 * 62; idx += 224) {
        const int rr = idx / 62, cc = idx % 62;
        const int gr = rr - 3, gc = cc - 3;
        float v = 0.f;
        if ((unsigned)gr < 56u && (unsigned)gc < 56u) v = xp[gr * 56 + gc];
        xs[idx] = v;
    }
    if (tid < 49) ws[tid] = g_dynw[(size_t)bc * NP + tid];
    __syncthreads();

    const int cg = tid / 56;
    const int col = tid % 56;

    float acc[14];
#pragma unroll
    for (int k = 0; k < 14; k++) acc[k] = 0.f;

    for (int dj = 0; dj < 7; dj++) {
        float cv[20];
#pragma unroll
        for (int m = 0; m < 20; m++)
            cv[m] = xs[(cg * 14 + m) * 62 + col + dj];
#pragma unroll
        for (int di = 0; di < 7; di++) {
            const float w = ws[di * 7 + dj];
#pragma unroll
            for (int k = 0; k < 14; k++)
                acc[k] = fmaf(cv[k + di], w, acc[k]);
        }
    }
    float* yp = y + (size_t)bc * (NH * NW);
#pragma unroll
    for (int k = 0; k < 14; k++)
        yp[(cg * 14 + k) * 56 + col] = acc[k];
}

// ---------------- launch ----------------
extern "C" void kernel_launch(void* const* d_in, const int* in_sizes, int n_in,
                              void* d_out, int out_size) {
    const float* x     = (const float*)d_in[0];
    const float* wdyn  = (const float*)d_in[1];
    const float* w1    = (const float*)d_in[2];
    const float* gamma = (const float*)d_in[3];
    const float* beta  = (const float*)d_in[4];
    const float* w2    = (const float*)d_in[5];
    const float* b2    = (const float*)d_in[6];
    float* y = (float*)d_out;

    wt_kernel<<<(W1N + W2DN + NC + 255) / 256, 256>>>(w1, w2, b2);
    pool_kernel<<<NB * NC, 416>>>(x);
    conv1_kernel<<<dim3(NSL, NB), 224>>>();
    ep1_kernel<<<392, 256>>>(gamma, beta);
    conv2_kernel<<<dim3(4, NB), 224>>>();
    mix_kernel<<<1568, 256>>>(wdyn);
    dw_kernel<<<NB * NC, 224>>>(x, y);
}

// round 4
// speedup vs baseline: 1.6920x; 1.1954x over previous
#include <cuda_runtime.h>
#include <math.h>

#define NB 32
#define NC 256
#define NH 56
#define NW 56
#define NP 49
#define CMID 64
#define NSL 8            // conv1 split-K slices (32 channels each)

// ---------------- scratch ----------------
__device__ float g_pooled[NB * NC * NP];
__device__ float g_w1t[2304 * CMID];            // [k=c*9+t][oc]
__device__ float g_w2d[576 * NC];               // [k=c*9+t][oc] (diff oc - (oc+256))
__device__ float g_b2d[NC];
__device__ float g_c1part[NB * CMID * NP * NSL];
__device__ float g_l2part[NB * NC * NP * 2];    // conv2-diff partials (2 ic-slices)

#define W1N (CMID * 2304)
#define W2DN (NC * 576)
#define WTN (W1N + W2DN + NC)
#define POOLBLKS (NB * NC)
#define WTBLKS ((WTN + 415) / 416)

// ---------------- kernel 0: pool (56x56 -> 7x7)  ||  weight prep ----------------
__global__ void prep_kernel(const float* __restrict__ x, const float* __restrict__ w1,
                            const float* __restrict__ w2, const float* __restrict__ b2) {
    const int tid = threadIdx.x;
    if (blockIdx.x < POOLBLKS) {
        __shared__ float srow[392];
        const int bc = blockIdx.x;
        if (tid < 392) {
            const int r = tid / 7, s = tid % 7;
            const float4* p = reinterpret_cast<const float4*>(
                x + (size_t)bc * (NH * NW) + r * NW + s * 8);
            float4 v0 = p[0], v1 = p[1];
            srow[tid] = (v0.x + v0.y + v0.z + v0.w) + (v1.x + v1.y + v1.z + v1.w);
        }
        __syncthreads();
        if (tid < NP) {
            const int wi = tid / 7, wj = tid % 7;
            float s = 0.f;
#pragma unroll
            for (int k = 0; k < 8; k++) s += srow[(wi * 8 + k) * 7 + wj];
            g_pooled[bc * NP + tid] = s * (1.0f / 64.0f);
        }
    } else {
        const int i = (blockIdx.x - POOLBLKS) * 416 + tid;
        if (i < W1N) {
            int oc = i / 2304, k = i % 2304;
            g_w1t[k * CMID + oc] = w1[i];
        } else if (i < W1N + W2DN) {
            int j = i - W1N;
            int oc = j / 576, k = j % 576;
            g_w2d[k * NC + oc] = w2[oc * 576 + k] - w2[(oc + 256) * 576 + k];
        } else if (i < WTN) {
            int oc = i - W1N - W2DN;
            g_b2d[oc] = b2[oc] - b2[oc + 256];
        }
    }
}

// ---------------- kernel 1: conv1 3x3 (256->64), split-K=8 ----------------
// grid (8 slices, 32 b), block 224: warp = output row, lane = oc pair
__global__ void __launch_bounds__(224, 2) conv1_kernel() {
    __shared__ float s_act[8 * 108];
    __shared__ float s_w[4608];     // 8 ch: (cl*9+t) x 64 oc
    const int sl = blockIdx.x, b = blockIdx.y;
    const int tid = threadIdx.x;
    const int r = tid >> 5, lane = tid & 31;

    float acc0[7], acc1[7];
#pragma unroll
    for (int i = 0; i < 7; i++) { acc0[i] = 0.f; acc1[i] = 0.f; }

    for (int chunk = 0; chunk < 4; chunk++) {
        __syncthreads();
        const int c0 = sl * 32 + chunk * 8;
        for (int idx = tid; idx < 8 * 81; idx += 224) {
            const int c = idx / 81, pp = idx % 81;
            const int pr = pp / 9, pc = pp % 9;
            float v = 0.f;
            if (pr >= 1 && pr <= 7 && pc >= 1 && pc <= 7)
                v = g_pooled[(b * NC + c0 + c) * NP + (pr - 1) * 7 + (pc - 1)];
            s_act[c * 108 + pr * 12 + pc] = v;
        }
        {
            const float4* src = reinterpret_cast<const float4*>(g_w1t + c0 * 9 * CMID);
            float4* dst = reinterpret_cast<float4*>(s_w);
            for (int idx = tid; idx < 1152; idx += 224) dst[idx] = src[idx];
        }
        __syncthreads();

#pragma unroll
        for (int cl = 0; cl < 8; cl++) {
            float aa[3][9];
#pragma unroll
            for (int ti = 0; ti < 3; ti++) {
                const float* rp = s_act + cl * 108 + (r + ti) * 12;
                float4 v0 = *reinterpret_cast<const float4*>(rp);
                float4 v1 = *reinterpret_cast<const float4*>(rp + 4);
                aa[ti][0] = v0.x; aa[ti][1] = v0.y; aa[ti][2] = v0.z; aa[ti][3] = v0.w;
                aa[ti][4] = v1.x; aa[ti][5] = v1.y; aa[ti][6] = v1.z; aa[ti][7] = v1.w;
                aa[ti][8] = rp[8];
            }
#pragma unroll
            for (int ti = 0; ti < 3; ti++) {
#pragma unroll
                for (int tj = 0; tj < 3; tj++) {
                    const float2 w = *reinterpret_cast<const float2*>(
                        s_w + (cl * 9 + ti * 3 + tj) * 64 + lane * 2);
#pragma unroll
                    for (int pj = 0; pj < 7; pj++) {
                        acc0[pj] = fmaf(aa[ti][pj + tj], w.x, acc0[pj]);
                        acc1[pj] = fmaf(aa[ti][pj + tj], w.y, acc1[pj]);
                    }
                }
            }
        }
    }
#pragma unroll
    for (int pj = 0; pj < 7; pj++) {
        const int p = r * 7 + pj;
        g_c1part[((size_t)(b * CMID + lane * 2) * NP + p) * NSL + sl] = acc0[pj];
        g_c1part[((size_t)(b * CMID + lane * 2 + 1) * NP + p) * NSL + sl] = acc1[pj];
    }
}

// ---------------- kernel 2: conv2-diff 3x3 (64->256), fused reduce+BN+GELU ----------------
// grid (4 oc-tiles of 64, 2 ic-slices, 32 b), block 224
__global__ void __launch_bounds__(224, 2) conv2_kernel(const float* __restrict__ gamma,
                                                       const float* __restrict__ beta) {
    __shared__ float s_act[8 * 108];
    __shared__ float s_w[4608];
    const int ot = blockIdx.x, ks = blockIdx.y, b = blockIdx.z;
    const int tid = threadIdx.x;
    const int r = tid >> 5, lane = tid & 31;

    float acc0[7], acc1[7];
#pragma unroll
    for (int i = 0; i < 7; i++) { acc0[i] = 0.f; acc1[i] = 0.f; }

    for (int chunk = 0; chunk < 4; chunk++) {
        __syncthreads();
        const int ic0 = ks * 32 + chunk * 8;
        for (int idx = tid; idx < 8 * 81; idx += 224) {
            const int c = idx / 81, pp = idx % 81;
            const int pr = pp / 9, pc = pp % 9;
            float v = 0.f;
            if (pr >= 1 && pr <= 7 && pc >= 1 && pc <= 7) {
                const int mid = ic0 + c;
                const float4* p8 = reinterpret_cast<const float4*>(
                    g_c1part + ((size_t)(b * CMID + mid) * NP + (pr - 1) * 7 + (pc - 1)) * NSL);
                float4 u = p8[0], w4 = p8[1];
                float s = ((u.x + u.y) + (u.z + u.w)) + ((w4.x + w4.y) + (w4.z + w4.w));
                float h = s * (gamma[mid] * rsqrtf(1.0f + 1e-5f)) + beta[mid];
                v = 0.5f * h * (1.0f + erff(h * 0.70710678118654752f));
            }
            s_act[c * 108 + pr * 12 + pc] = v;
        }
        for (int idx = tid; idx < 1152; idx += 224) {
            const int kk = idx >> 4, c4 = idx & 15;
            reinterpret_cast<float4*>(s_w)[idx] = *reinterpret_cast<const float4*>(
                g_w2d + (ic0 * 9 + kk) * NC + ot * 64 + c4 * 4);
        }
        __syncthreads();

#pragma unroll
        for (int cl = 0; cl < 8; cl++) {
            float aa[3][9];
#pragma unroll
            for (int ti = 0; ti < 3; ti++) {
                const float* rp = s_act + cl * 108 + (r + ti) * 12;
                float4 v0 = *reinterpret_cast<const float4*>(rp);
                float4 v1 = *reinterpret_cast<const float4*>(rp + 4);
                aa[ti][0] = v0.x; aa[ti][1] = v0.y; aa[ti][2] = v0.z; aa[ti][3] = v0.w;
                aa[ti][4] = v1.x; aa[ti][5] = v1.y; aa[ti][6] = v1.z; aa[ti][7] = v1.w;
                aa[ti][8] = rp[8];
            }
#pragma unroll
            for (int ti = 0; ti < 3; ti++) {
#pragma unroll
                for (int tj = 0; tj < 3; tj++) {
                    const float2 w = *reinterpret_cast<const float2*>(
                        s_w + (cl * 9 + ti * 3 + tj) * 64 + lane * 2);
#pragma unroll
                    for (int pj = 0; pj < 7; pj++) {
                        acc0[pj] = fmaf(aa[ti][pj + tj], w.x, acc0[pj]);
                        acc1[pj] = fmaf(aa[ti][pj + tj], w.y, acc1[pj]);
                    }
                }
            }
        }
    }

    const int oc0 = ot * 64 + lane * 2;
#pragma unroll
    for (int pj = 0; pj < 7; pj++) {
        const int p = r * 7 + pj;
        g_l2part[((size_t)(b * NC + oc0) * NP + p) * 2 + ks] = acc0[pj];
        g_l2part[((size_t)(b * NC + oc0 + 1) * NP + p) * 2 + ks] = acc1[pj];
    }
}

// ---------------- kernel 3: dw 7x7 depthwise, fused sigmoid-gate mix ----------------
__global__ void __launch_bounds__(224) dw_kernel(const float* __restrict__ x,
                                                 const float* __restrict__ wdyn,
                                                 float* __restrict__ y) {
    __shared__ float xs[62 * 62];
    __shared__ float ws[49];
    const int bc = blockIdx.x;
    const int tid = threadIdx.x;

    const float* xp = x + (size_t)bc * (NH * NW);
    for (int idx = tid; idx < 62 * 62; idx += 224) {
        const int rr = idx / 62, cc = idx % 62;
        const int gr = rr - 3, gc = cc - 3;
        float v = 0.f;
        if ((unsigned)gr < 56u && (unsigned)gc < 56u) v = xp[gr * 56 + gc];
        xs[idx] = v;
    }
    if (tid < 49) {
        const int c = bc & (NC - 1);
        const float2 lp = *reinterpret_cast<const float2*>(g_l2part + ((size_t)bc * NP + tid) * 2);
        const float ld = lp.x + lp.y + g_b2d[c];
        const float s = 1.0f / (1.0f + expf(-ld));
        const float w0 = wdyn[c * NP + tid];
        const float w1 = wdyn[NC * NP + c * NP + tid];
        ws[tid] = s * w0 + (1.0f - s) * w1;
    }
    __syncthreads();

    const int cg = tid / 56;
    const int col = tid % 56;

    float acc[14];
#pragma unroll
    for (int k = 0; k < 14; k++) acc[k] = 0.f;

    for (int dj = 0; dj < 7; dj++) {
        float cv[20];
#pragma unroll
        for (int m = 0; m < 20; m++)
            cv[m] = xs[(cg * 14 + m) * 62 + col + dj];
#pragma unroll
        for (int di = 0; di < 7; di++) {
            const float w = ws[di * 7 + dj];
#pragma unroll
            for (int k = 0; k < 14; k++)
                acc[k] = fmaf(cv[k + di], w, acc[k]);
        }
    }
    float* yp = y + (size_t)bc * (NH * NW);
#pragma unroll
    for (int k = 0; k < 14; k++)
        yp[(cg * 14 + k) * 56 + col] = acc[k];
}

// ---------------- launch ----------------
extern "C" void kernel_launch(void* const* d_in, const int* in_sizes, int n_in,
                              void* d_out, int out_size) {
    const float* x     = (const float*)d_in[0];
    const float* wdyn  = (const float*)d_in[1];
    const float* w1    = (const float*)d_in[2];
    const float* gamma = (const float*)d_in[3];
    const float* beta  = (const float*)d_in[4];
    const float* w2    = (const float*)d_in[5];
    const float* b2    = (const float*)d_in[6];
    float* y = (float*)d_out;

    prep_kernel<<<POOLBLKS + WTBLKS, 416>>>(x, w1, w2, b2);
    conv1_kernel<<<dim3(NSL, NB), 224>>>();
    conv2_kernel<<<dim3(4, 2, NB), 224>>>(gamma, beta);
    dw_kernel<<<NB * NC, 224>>>(x, wdyn, y);
}